// round 10
// baseline (speedup 1.0000x reference)
#include <cuda_runtime.h>
#include <cstdint>

// LJ constants (sigma = 1, epsilon = 1, cutoff = 5)
// SHIFT = 4*((1/5)^12 - (1/5)^6)
static __device__ __constant__ float c_shift = 4.0f * (float)(4.096e-09 - 6.4e-05);

// Node 1: zero the per-atom accumulators (runs concurrently with the PDL
// prologue of the main kernel; atomics wait on it via GridDependencySync).
__global__ void __launch_bounds__(256) zero_kernel(
    float4* __restrict__ out4, int n4,
    float* __restrict__ out, int n)
{
    int i = blockIdx.x * blockDim.x + threadIdx.x;
    if (i < n4) out4[i] = make_float4(0.f, 0.f, 0.f, 0.f);
    int r = 4 * n4 + i;
    if (r < n) out[r] = 0.f;
}

__device__ __forceinline__ float lj_half_energy(float x, float y, float z) {
    float r2 = fmaf(x, x, fmaf(y, y, z * z));
    float inv = 1.0f / r2;              // (sigma/r)^2 with sigma = 1
    float sr6 = inv * inv * inv;        // (sigma/r)^6
    float e = fmaf(4.0f, fmaf(sr6, sr6, -sr6), -c_shift);
    return 0.5f * e;
}

// Main kernel: 4 edges/thread, block = 256, one-shot grid, REDG atomics.
// PDL-structured: dtype probe + all loads + compute happen BEFORE
// cudaGridDependencySynchronize(); only the atomics wait for the zero kernel.
__global__ void __launch_bounds__(256) lj_kernel(
    const float4* __restrict__ d4,
    const void* __restrict__ fa,
    const void* __restrict__ sa,
    float* __restrict__ out,
    int n_quads)
{
    // Per-CTA dtype probe (independent of the zero kernel, so it can run in
    // the PDL prologue). int64-LE with values < 2^31 -> odd 32-bit words all
    // zero; int32 indices in [0, 100000): all-zero prob ~(1e-5)^16.
    __shared__ int s_idx64;
    if (threadIdx.x == 0) {
        const unsigned int* p = (const unsigned int*)fa;
        unsigned int acc = 0;
#pragma unroll
        for (int k = 0; k < 16; k++) acc |= p[2 * k + 1];
        s_idx64 = (acc == 0) ? 1 : 0;
    }
    __syncthreads();

    int i = blockIdx.x * blockDim.x + threadIdx.x;
    if (i >= n_quads) {
        cudaGridDependencySynchronize();
        return;
    }

    // 4 edges = 12 floats = 3 x float4, fully coalesced.
    float4 a = d4[3 * (size_t)i + 0];
    float4 b = d4[3 * (size_t)i + 1];
    float4 c = d4[3 * (size_t)i + 2];

    float h0 = lj_half_energy(a.x, a.y, a.z);
    float h1 = lj_half_energy(a.w, b.x, b.y);
    float h2 = lj_half_energy(b.z, b.w, c.x);
    float h3 = lj_half_energy(c.y, c.z, c.w);

    if (!s_idx64) {
        int4 f = ((const int4*)fa)[i];
        int4 s = ((const int4*)sa)[i];
        // Atomics must not start until the zero kernel has finished.
        cudaGridDependencySynchronize();
        atomicAdd(out + f.x, h0); atomicAdd(out + s.x, h0);
        atomicAdd(out + f.y, h1); atomicAdd(out + s.y, h1);
        atomicAdd(out + f.z, h2); atomicAdd(out + s.z, h2);
        atomicAdd(out + f.w, h3); atomicAdd(out + s.w, h3);
    } else {
        longlong2 f01 = ((const longlong2*)fa)[2 * (size_t)i + 0];
        longlong2 f23 = ((const longlong2*)fa)[2 * (size_t)i + 1];
        longlong2 s01 = ((const longlong2*)sa)[2 * (size_t)i + 0];
        longlong2 s23 = ((const longlong2*)sa)[2 * (size_t)i + 1];
        cudaGridDependencySynchronize();
        atomicAdd(out + f01.x, h0); atomicAdd(out + s01.x, h0);
        atomicAdd(out + f01.y, h1); atomicAdd(out + s01.y, h1);
        atomicAdd(out + f23.x, h2); atomicAdd(out + s23.x, h2);
        atomicAdd(out + f23.y, h3); atomicAdd(out + s23.y, h3);
    }
}

// Scalar tail for n_edges not divisible by 4 (skipped at capture when rem==0).
__global__ void lj_tail_kernel(
    const float* __restrict__ dist,
    const void* __restrict__ fa,
    const void* __restrict__ sa,
    float* __restrict__ out,
    int start, int n_edges)
{
    __shared__ int s_idx64;
    if (threadIdx.x == 0) {
        const unsigned int* p = (const unsigned int*)fa;
        unsigned int acc = 0;
#pragma unroll
        for (int k = 0; k < 16; k++) acc |= p[2 * k + 1];
        s_idx64 = (acc == 0) ? 1 : 0;
    }
    __syncthreads();

    int e = start + blockIdx.x * blockDim.x + threadIdx.x;
    if (e >= n_edges) return;
    float x = dist[3 * (size_t)e + 0];
    float y = dist[3 * (size_t)e + 1];
    float z = dist[3 * (size_t)e + 2];
    float h = lj_half_energy(x, y, z);
    long long i0, i1;
    if (s_idx64) {
        i0 = ((const long long*)fa)[e];
        i1 = ((const long long*)sa)[e];
    } else {
        i0 = ((const int*)fa)[e];
        i1 = ((const int*)sa)[e];
    }
    atomicAdd(out + i0, h);
    atomicAdd(out + i1, h);
}

extern "C" void kernel_launch(void* const* d_in, const int* in_sizes, int n_in,
                              void* d_out, int out_size)
{
    const float* dist = (const float*)d_in[0];
    const void*  fa   = d_in[1];
    const void*  sa   = d_in[2];
    float* out = (float*)d_out;

    int n_edges = in_sizes[1];  // element count of first_atom

    // Node 1: zero accumulators.
    {
        int n4 = out_size / 4;
        int work = (n4 > 0) ? n4 : 1;
        int blocks = (work + 255) / 256;
        zero_kernel<<<blocks, 256>>>((float4*)d_out, n4, out, out_size);
    }

    // Node 2: main kernel with programmatic dependent launch — its prologue
    // (probe + loads + FMA) overlaps the zero kernel; atomics gated by
    // cudaGridDependencySynchronize().
    int quads = n_edges / 4;
    if (quads > 0) {
        int blocks = (quads + 255) / 256;

        cudaLaunchConfig_t cfg = {};
        cfg.gridDim = dim3((unsigned)blocks, 1, 1);
        cfg.blockDim = dim3(256, 1, 1);
        cfg.dynamicSmemBytes = 0;
        cfg.stream = 0;
        cudaLaunchAttribute attrs[1];
        attrs[0].id = cudaLaunchAttributeProgrammaticStreamSerialization;
        attrs[0].val.programmaticStreamSerializationAllowed = 1;
        cfg.attrs = attrs;
        cfg.numAttrs = 1;

        cudaError_t err = cudaLaunchKernelEx(&cfg, lj_kernel,
                                             (const float4*)dist, fa, sa, out, quads);
        if (err != cudaSuccess) {
            // Fallback: plain serialized launch (identical results).
            lj_kernel<<<blocks, 256>>>((const float4*)dist, fa, sa, out, quads);
        }
    }

    // Tail only if n_edges % 4 != 0 (not the case for 6.4M edges).
    int rem_start = quads * 4;
    if (rem_start < n_edges) {
        int rem = n_edges - rem_start;
        lj_tail_kernel<<<(rem + 255) / 256, 256>>>(dist, fa, sa, out, rem_start, n_edges);
    }
}